// round 1
// baseline (speedup 1.0000x reference)
#include <cuda_runtime.h>
#include <cuda_bf16.h>

// BrainDecayAttention: B=16, H=8 (4 short + 4 long), N=1024, D=64, fp32.
// Outputs packed: combined_out [B,H,N,D] then combined_w [B,H,N,N].

#define B_  16
#define H_  8
#define HH_ 4
#define N_  1024
#define D_  64
#define TR  32          // rows (n) per CTA
#define TM  64          // m-tile
#define KPAD 65         // padded row stride for K/V/Q tiles (odd -> conflict-free)

// dynamic smem layout (floats):
//   Ebuf : TR * N_            = 32768
//   Kt   : TM * KPAD          =  4160   (reused for V in phase D)
//   Qt   : TR * KPAD          =  2080
//   inv  : TR                 =    32
#define SMEM_FLOATS (TR*N_ + TM*KPAD + TR*KPAD + TR)
#define SMEM_BYTES  (SMEM_FLOATS * 4)

__global__ void __launch_bounds__(256, 1)
bda_kernel(const float* __restrict__ q,
           const float* __restrict__ k,
           const float* __restrict__ v,
           const float* __restrict__ sph,
           const float* __restrict__ hop,
           const float* __restrict__ gam,
           float* __restrict__ out_o,
           float* __restrict__ out_w)
{
    extern __shared__ float sm[];
    float* Ebuf = sm;                       // [TR][N_]
    float* Kt   = sm + TR*N_;               // [TM][KPAD]
    float* Qt   = Kt + TM*KPAD;             // [TR][KPAD]
    float* inv  = Qt + TR*KPAD;             // [TR]

    const int blk   = blockIdx.x;
    const int tileb = blk & 31;             // N_/TR = 32 tiles
    const int h     = (blk >> 5) & 7;
    const int b     = blk >> 8;
    const int n0    = tileb * TR;

    const int tid = threadIdx.x;
    const int tx  = tid & 31;
    const int ty  = tid >> 5;

    const float scale = 0.125f;             // 1/sqrt(64)
    const bool isShort = (h < HH_);
    float hopv = 0.f, lgg = 0.f;
    if (isShort) {
        hopv = hop[h];
        float g = 1.f / (1.f + __expf(-gam[h]));   // sigmoid
        lgg = __log2f(g);                           // log2(gamma)
    }

    const size_t bh  = (size_t)b * H_ + h;
    const float* qb  = q + bh * (size_t)N_ * D_;
    const float* kb  = k + bh * (size_t)N_ * D_;
    const float* vb  = v + bh * (size_t)N_ * D_;
    const float* sphb = sph + (size_t)b * N_ * N_;

    // ---- load Q tile [TR][D] (row-major, pad KPAD) ----
    for (int idx = tid; idx < TR*D_; idx += 256) {
        int r = idx >> 6, d = idx & 63;
        Qt[r*KPAD + d] = qb[(size_t)(n0 + r)*D_ + d];
    }

    float psum[4] = {0.f, 0.f, 0.f, 0.f};

    // ================= Phase A: S = QK^T, modulate, exp, buffer =================
    for (int mt = 0; mt < N_/TM; ++mt) {
        __syncthreads();
        for (int idx = tid; idx < TM*D_; idx += 256) {
            int m = idx >> 6, d = idx & 63;
            Kt[m*KPAD + d] = kb[(size_t)(mt*TM + m)*D_ + d];
        }
        __syncthreads();

        float acc[4][2] = {};
        #pragma unroll 4
        for (int d = 0; d < D_; ++d) {
            float k0 = Kt[tx*KPAD + d];          // lanes -> distinct banks (pad 65)
            float k1 = Kt[(tx+32)*KPAD + d];
            #pragma unroll
            for (int i = 0; i < 4; ++i) {
                float qv = Qt[(4*ty+i)*KPAD + d];   // warp broadcast
                acc[i][0] = fmaf(qv, k0, acc[i][0]);
                acc[i][1] = fmaf(qv, k1, acc[i][1]);
            }
        }

        #pragma unroll
        for (int i = 0; i < 4; ++i) {
            const int r    = 4*ty + i;
            const int nrow = n0 + r;
            float s0 = acc[i][0] * scale;
            float s1 = acc[i][1] * scale;
            if (isShort) {
                float sp0 = __ldg(&sphb[(size_t)nrow*N_ + mt*TM + tx]);
                float sp1 = __ldg(&sphb[(size_t)nrow*N_ + mt*TM + tx + 32]);
                float dec0 = fmaxf(sp0 - hopv, 0.f);
                float dec1 = fmaxf(sp1 - hopv, 0.f);
                s0 *= exp2f(dec0 * lgg);            // gamma^decay
                s1 *= exp2f(dec1 * lgg);
            }
            // logits bounded ~|s|<=6 -> safe without max subtraction
            float e0 = __expf(s0);
            float e1 = __expf(s1);
            Ebuf[r*N_ + mt*TM + tx]      = e0;
            Ebuf[r*N_ + mt*TM + tx + 32] = e1;
            psum[i] += e0 + e1;
        }
    }

    // ================= Phase B: row sums -> inverse =================
    #pragma unroll
    for (int i = 0; i < 4; ++i) {
        float s = psum[i];
        #pragma unroll
        for (int off = 16; off; off >>= 1)
            s += __shfl_xor_sync(0xffffffffu, s, off);
        if (tx == 0) inv[4*ty + i] = 1.0f / s;
    }
    __syncthreads();

    // ================= Phase C: write normalized W =================
    {
        float* wb = out_w + ((bh * N_ + n0) * (size_t)N_);
        for (int idx = tid; idx < TR*N_; idx += 256) {
            int r = idx >> 10;                    // N_ = 1024
            wb[idx] = Ebuf[idx] * inv[r];
        }
    }

    // ================= Phase D: O = (E @ V) * inv =================
    float acc2[4][2] = {};
    for (int mt = 0; mt < N_/TM; ++mt) {
        __syncthreads();
        for (int idx = tid; idx < TM*D_; idx += 256) {
            int m = idx >> 6, d = idx & 63;
            Kt[m*KPAD + d] = vb[(size_t)(mt*TM + m)*D_ + d];   // reuse Kt for V
        }
        __syncthreads();

        #pragma unroll 4
        for (int mm = 0; mm < TM; ++mm) {
            float v0 = Kt[mm*KPAD + tx];
            float v1 = Kt[mm*KPAD + tx + 32];
            #pragma unroll
            for (int i = 0; i < 4; ++i) {
                float e = Ebuf[(4*ty+i)*N_ + mt*TM + mm];      // warp broadcast
                acc2[i][0] = fmaf(e, v0, acc2[i][0]);
                acc2[i][1] = fmaf(e, v1, acc2[i][1]);
            }
        }
    }

    {
        float* ob = out_o + ((bh * N_ + n0) * (size_t)D_);
        #pragma unroll
        for (int i = 0; i < 4; ++i) {
            const int r = 4*ty + i;
            const float iv = inv[r];
            ob[(size_t)r*D_ + tx]      = acc2[i][0] * iv;
            ob[(size_t)r*D_ + tx + 32] = acc2[i][1] * iv;
        }
    }
}

extern "C" void kernel_launch(void* const* d_in, const int* in_sizes, int n_in,
                              void* d_out, int out_size)
{
    (void)in_sizes; (void)n_in; (void)out_size;
    const float* q   = (const float*)d_in[0];
    const float* k   = (const float*)d_in[1];
    const float* v   = (const float*)d_in[2];
    const float* sph = (const float*)d_in[3];
    const float* hop = (const float*)d_in[4];
    const float* gam = (const float*)d_in[5];

    float* out_o = (float*)d_out;
    float* out_w = out_o + (size_t)B_ * H_ * N_ * D_;

    cudaFuncSetAttribute(bda_kernel,
                         cudaFuncAttributeMaxDynamicSharedMemorySize,
                         SMEM_BYTES);

    dim3 grid(B_ * H_ * (N_ / TR));   // 4096
    bda_kernel<<<grid, 256, SMEM_BYTES>>>(q, k, v, sph, hop, gam, out_o, out_w);
}

// round 2
// speedup vs baseline: 2.2840x; 2.2840x over previous
#include <cuda_runtime.h>
#include <cuda_bf16.h>

// BrainDecayAttention: B=16, H=8 (4 short + 4 long), N=1024, D=64, fp32.
// Output packed: combined_out [B,H,N,D] then combined_w [B,H,N,N].

#define B_  16
#define H_  8
#define HH_ 4
#define N_  1024
#define D_  64
#define TR  32          // rows (n) per CTA
#define TM  128         // m-tile (K rows / V rows per stage)
#define KP  68          // pad for Kt/Qt (float4-friendly, conflict-free in 8-lane phases)
#define KPV 65          // pad for Vt (scalar conflict-free)

// dynamic smem (floats):
//   Ebuf : TR*N_          = 32768
//   Kt   : 2*TM*KP        = 17408  (double-buffered; reused as Vt with KPV)
//   Qt   : TR*KP          =  2176
//   inv  : TR             =    32
#define SMEM_FLOATS (TR*N_ + 2*TM*KP + TR*KP + TR)
#define SMEM_BYTES  (SMEM_FLOATS * 4)

__global__ void __launch_bounds__(256, 1)
bda_kernel(const float* __restrict__ q,
           const float* __restrict__ k,
           const float* __restrict__ v,
           const float* __restrict__ sph,
           const float* __restrict__ hop,
           const float* __restrict__ gam,
           float* __restrict__ out_o,
           float* __restrict__ out_w)
{
    extern __shared__ float sm[];
    float* Ebuf = sm;                       // [TR][N_]
    float* Kt   = sm + TR*N_;               // [2][TM][KP]  (or [2][TM][KPV] as Vt)
    float* Qt   = Kt + 2*TM*KP;             // [TR][KP]
    float* inv  = Qt + TR*KP;               // [TR]

    const int blk   = blockIdx.x;
    const int tileb = blk & 31;             // 32 row-tiles
    const int h     = (blk >> 5) & 7;
    const int b     = blk >> 8;
    const int n0    = tileb * TR;

    const int tid = threadIdx.x;
    const int tx  = tid & 31;
    const int w   = tid >> 5;               // warp id: owns rows 4w..4w+3

    const float scale = 0.125f;             // 1/sqrt(64)
    const bool isShort = (h < HH_);
    float hopv = 0.f, lgg = 0.f;
    if (isShort) {
        hopv = hop[h];
        float g = 1.f / (1.f + __expf(-gam[h]));
        lgg = __log2f(g);
    }

    const size_t bh   = (size_t)b * H_ + h;
    const float* qb   = q + bh * (size_t)N_ * D_;
    const float* kb   = k + bh * (size_t)N_ * D_;
    const float* vb   = v + bh * (size_t)N_ * D_;
    const float* sphb = sph + ((size_t)b * N_ + n0) * N_;

    // ---- load Q tile [TR][D] into Qt (pad KP) ----
    for (int idx = tid; idx < TR*D_; idx += 256) {
        int r = idx >> 6, d = idx & 63;
        Qt[r*KP + d] = qb[(size_t)(n0 + r)*D_ + d];
    }

    // ---- prologue: K tile 0 into Kt[0] ----
    {
        const float* src = kb;              // tile 0
        #pragma unroll
        for (int t = 0; t < 8; ++t) {
            int lin = t*256 + tid;          // 2048 float4 per tile
            int row = lin >> 4, c4 = lin & 15;
            float4 val = *(const float4*)&src[(size_t)row*D_ + c4*4];
            *(float4*)&Kt[row*KP + c4*4] = val;
        }
    }
    __syncthreads();

    float psum[4] = {0.f, 0.f, 0.f, 0.f};

    // ================= Phase A: E = exp(mod(QK^T * scale)) -> Ebuf =================
    for (int mt = 0; mt < N_/TM; ++mt) {
        const int cur = mt & 1;
        float* Kc = Kt + cur*TM*KP;

        // prefetch next K tile into registers (overlaps compute)
        float4 pre[8];
        if (mt < N_/TM - 1) {
            const float* src = kb + (size_t)(mt+1)*TM*D_;
            #pragma unroll
            for (int t = 0; t < 8; ++t) {
                int lin = t*256 + tid;
                int row = lin >> 4, c4 = lin & 15;
                pre[t] = *(const float4*)&src[(size_t)row*D_ + c4*4];
            }
        }

        // compute: acc[4 rows][4 cols], cols = tx + 32c
        float acc[4][4] = {};
        #pragma unroll
        for (int d4 = 0; d4 < D_/4; ++d4) {
            float4 kr[4];
            #pragma unroll
            for (int c = 0; c < 4; ++c)
                kr[c] = *(const float4*)&Kc[(tx + 32*c)*KP + 4*d4];
            #pragma unroll
            for (int i = 0; i < 4; ++i) {
                float4 qv = *(const float4*)&Qt[(4*w + i)*KP + 4*d4];
                #pragma unroll
                for (int c = 0; c < 4; ++c) {
                    acc[i][c] = fmaf(qv.x, kr[c].x, acc[i][c]);
                    acc[i][c] = fmaf(qv.y, kr[c].y, acc[i][c]);
                    acc[i][c] = fmaf(qv.z, kr[c].z, acc[i][c]);
                    acc[i][c] = fmaf(qv.w, kr[c].w, acc[i][c]);
                }
            }
        }

        // epilogue: modulate, exp, buffer, partial sums
        #pragma unroll
        for (int i = 0; i < 4; ++i) {
            const int r = 4*w + i;
            const float* sprow = sphb + (size_t)r*N_ + mt*TM;
            float*       erow  = Ebuf + r*N_ + mt*TM;
            #pragma unroll
            for (int c = 0; c < 4; ++c) {
                int col = tx + 32*c;
                float s = acc[i][c] * scale;
                if (isShort) {
                    float sp  = __ldg(&sprow[col]);
                    float dec = fmaxf(sp - hopv, 0.f);
                    s *= exp2f(dec * lgg);          // gamma^decay
                }
                float e = __expf(s);                // logits bounded: no max needed
                erow[col] = e;
                psum[i] += e;
            }
        }

        if (mt < N_/TM - 1) {
            __syncthreads();                        // all readers of Kt[cur^1] done
            float* Kn = Kt + (cur^1)*TM*KP;
            #pragma unroll
            for (int t = 0; t < 8; ++t) {
                int lin = t*256 + tid;
                int row = lin >> 4, c4 = lin & 15;
                *(float4*)&Kn[row*KP + c4*4] = pre[t];
            }
            __syncthreads();                        // writes visible
        }
    }

    // ================= Phase B: row sums -> inverse =================
    #pragma unroll
    for (int i = 0; i < 4; ++i) {
        float s = psum[i];
        #pragma unroll
        for (int off = 16; off; off >>= 1)
            s += __shfl_xor_sync(0xffffffffu, s, off);
        if (tx == 0) inv[4*w + i] = 1.0f / s;
    }
    __syncthreads();

    // ---- prefetch V tile 0 (overlaps Phase C stores) ----
    float4 vpre[8];
    {
        const float* src = vb;
        #pragma unroll
        for (int t = 0; t < 8; ++t) {
            int lin = t*256 + tid;
            int row = lin >> 4, c4 = lin & 15;
            vpre[t] = *(const float4*)&src[(size_t)row*D_ + c4*4];
        }
    }

    // ================= Phase C: write normalized W (float4 stores) =================
    {
        float4* wb = (float4*)(out_w + ((bh * N_ + n0) * (size_t)N_));
        const float4* eb = (const float4*)Ebuf;
        for (int idx = tid; idx < TR*N_/4; idx += 256) {
            int r = idx >> 8;                       // 256 float4 per row
            float iv = inv[r];
            float4 e = eb[idx];
            e.x *= iv; e.y *= iv; e.z *= iv; e.w *= iv;
            wb[idx] = e;
        }
    }

    // store V tile 0 (scalar, pad KPV)
    {
        float* Vn = Kt;                             // buffer 0, KPV layout
        #pragma unroll
        for (int t = 0; t < 8; ++t) {
            int lin = t*256 + tid;
            int row = lin >> 4, c4 = lin & 15;
            Vn[row*KPV + c4*4 + 0] = vpre[t].x;
            Vn[row*KPV + c4*4 + 1] = vpre[t].y;
            Vn[row*KPV + c4*4 + 2] = vpre[t].z;
            Vn[row*KPV + c4*4 + 3] = vpre[t].w;
        }
    }
    __syncthreads();

    // ================= Phase D: O = (E @ V) * inv =================
    float acc2[4][2] = {};
    for (int mt = 0; mt < N_/TM; ++mt) {
        const int cur = mt & 1;
        const float* Vc = Kt + cur*TM*KPV;

        if (mt < N_/TM - 1) {
            const float* src = vb + (size_t)(mt+1)*TM*D_;
            #pragma unroll
            for (int t = 0; t < 8; ++t) {
                int lin = t*256 + tid;
                int row = lin >> 4, c4 = lin & 15;
                vpre[t] = *(const float4*)&src[(size_t)row*D_ + c4*4];
            }
        }

        #pragma unroll 4
        for (int m4 = 0; m4 < TM/4; ++m4) {
            float e4[4][4];
            #pragma unroll
            for (int i = 0; i < 4; ++i)
                *(float4*)e4[i] = *(const float4*)&Ebuf[(4*w + i)*N_ + mt*TM + 4*m4];
            #pragma unroll
            for (int j = 0; j < 4; ++j) {
                float v0 = Vc[(4*m4 + j)*KPV + tx];
                float v1 = Vc[(4*m4 + j)*KPV + tx + 32];
                #pragma unroll
                for (int i = 0; i < 4; ++i) {
                    acc2[i][0] = fmaf(e4[i][j], v0, acc2[i][0]);
                    acc2[i][1] = fmaf(e4[i][j], v1, acc2[i][1]);
                }
            }
        }

        if (mt < N_/TM - 1) {
            __syncthreads();
            float* Vn = Kt + (cur^1)*TM*KPV;
            #pragma unroll
            for (int t = 0; t < 8; ++t) {
                int lin = t*256 + tid;
                int row = lin >> 4, c4 = lin & 15;
                Vn[row*KPV + c4*4 + 0] = vpre[t].x;
                Vn[row*KPV + c4*4 + 1] = vpre[t].y;
                Vn[row*KPV + c4*4 + 2] = vpre[t].z;
                Vn[row*KPV + c4*4 + 3] = vpre[t].w;
            }
            __syncthreads();
        }
    }

    {
        float* ob = out_o + ((bh * N_ + n0) * (size_t)D_);
        #pragma unroll
        for (int i = 0; i < 4; ++i) {
            const int r = 4*w + i;
            const float iv = inv[r];
            ob[(size_t)r*D_ + tx]      = acc2[i][0] * iv;
            ob[(size_t)r*D_ + tx + 32] = acc2[i][1] * iv;
        }
    }
}

extern "C" void kernel_launch(void* const* d_in, const int* in_sizes, int n_in,
                              void* d_out, int out_size)
{
    (void)in_sizes; (void)n_in; (void)out_size;
    const float* q   = (const float*)d_in[0];
    const float* k   = (const float*)d_in[1];
    const float* v   = (const float*)d_in[2];
    const float* sph = (const float*)d_in[3];
    const float* hop = (const float*)d_in[4];
    const float* gam = (const float*)d_in[5];

    float* out_o = (float*)d_out;
    float* out_w = out_o + (size_t)B_ * H_ * N_ * D_;

    cudaFuncSetAttribute(bda_kernel,
                         cudaFuncAttributeMaxDynamicSharedMemorySize,
                         SMEM_BYTES);

    dim3 grid(B_ * H_ * (N_ / TR));   // 4096
    bda_kernel<<<grid, 256, SMEM_BYTES>>>(q, k, v, sph, hop, gam, out_o, out_w);
}

// round 9
// speedup vs baseline: 2.5715x; 1.1259x over previous
#include <cuda_runtime.h>
#include <cuda_bf16.h>
#include <cstdint>

// BrainDecayAttention via mma.sync bf16 split-precision (portable PTX, no 'a' features).
// B=16 H=8 N=1024 D=64 fp32. Grid 4096 = (b, h, 32-row q-tile), 256 threads.

#define Bn 16
#define Hn 8
#define Nn 1024
#define Dn 64
#define TR 32
#define NTILES 8

// ---- smem byte layout ----
#define RS_OFF   0                        // 32 floats
#define TAB_OFF  128                      // 8 floats
#define OSM_OFF  160                      // 2048 floats = 8192 B
#define SPX_OFF  8352                     // 2 x 4096 B sph idx tiles
#define QH_OFF   16544                    // 32 rows x 144 B = 4608
#define QL_OFF   (QH_OFF + 4608)
#define EH_OFF   (QL_OFF + 4608)          // 32 rows x 2064 B = 66048
#define EL_OFF   (EH_OFF + 66048)
#define KB_OFF   (EL_OFF + 66048)         // 2 buffers x 36864 (K hi/lo or V^T hi/lo)
#define SMEM_TOTAL (KB_OFF + 2*36864)     // 231584 B

static __device__ __forceinline__ void mmabf(float* c, const uint32_t* a,
                                             uint32_t b0, uint32_t b1){
    asm volatile("mma.sync.aligned.m16n8k16.row.col.f32.bf16.bf16.f32 "
        "{%0,%1,%2,%3}, {%4,%5,%6,%7}, {%8,%9}, {%0,%1,%2,%3};"
        : "+f"(c[0]), "+f"(c[1]), "+f"(c[2]), "+f"(c[3])
        : "r"(a[0]), "r"(a[1]), "r"(a[2]), "r"(a[3]), "r"(b0), "r"(b1));
}

static __device__ __forceinline__ void split8(const float* f, uint32_t* hw, uint32_t* lw){
    #pragma unroll
    for (int j = 0; j < 4; ++j) {
        float2 xy = make_float2(f[2*j], f[2*j+1]);
        __nv_bfloat162 hh = __float22bfloat162_rn(xy);
        float2 hf = __bfloat1622float2(hh);
        __nv_bfloat162 ll = __float22bfloat162_rn(make_float2(xy.x - hf.x, xy.y - hf.y));
        hw[j] = *(uint32_t*)&hh;
        lw[j] = *(uint32_t*)&ll;
    }
}

// K-style tile [rows x 64] fp32 -> hi/lo bf16, row stride 144 B
template<int NCH>
static __device__ __forceinline__ void kload(const float* __restrict__ src, int tid, float4* pre){
    #pragma unroll
    for (int i = 0; i < NCH; ++i) {
        int c = i*256 + tid, row = c >> 3, u = c & 7;
        const float4* p = (const float4*)(src + row*64 + u*8);
        pre[2*i] = p[0]; pre[2*i+1] = p[1];
    }
}
template<int NCH>
static __device__ __forceinline__ void kstore(const float4* pre, char* dh, char* dl, int tid){
    #pragma unroll
    for (int i = 0; i < NCH; ++i) {
        int c = i*256 + tid, row = c >> 3, u = c & 7;
        float f[8] = {pre[2*i].x, pre[2*i].y, pre[2*i].z, pre[2*i].w,
                      pre[2*i+1].x, pre[2*i+1].y, pre[2*i+1].z, pre[2*i+1].w};
        uint32_t hw[4], lw[4];
        split8(f, hw, lw);
        *(uint4*)(dh + row*144 + u*16) = make_uint4(hw[0], hw[1], hw[2], hw[3]);
        *(uint4*)(dl + row*144 + u*16) = make_uint4(lw[0], lw[1], lw[2], lw[3]);
    }
}

// V tile [128 s x 64 d] fp32 -> V^T hi/lo bf16 [64 d x 128 s], row stride 272 B
static __device__ __forceinline__ void vload(const float* __restrict__ vsrc, int tid, float4* pre){
    int s = tid >> 1, d0 = (tid & 1)*32;
    const float4* p = (const float4*)(vsrc + s*64 + d0);
    #pragma unroll
    for (int j = 0; j < 8; ++j) pre[j] = p[j];
}
static __device__ __forceinline__ void vstore(const float4* pre, char* dh, char* dl, int tid){
    int s = tid >> 1, d0 = (tid & 1)*32;
    #pragma unroll
    for (int j = 0; j < 8; ++j) {
        float f[4] = {pre[j].x, pre[j].y, pre[j].z, pre[j].w};
        #pragma unroll
        for (int e = 0; e < 4; ++e) {
            int d = d0 + j*4 + e;
            __nv_bfloat16 hx = __float2bfloat16_rn(f[e]);
            float rxv = f[e] - __bfloat162float(hx);
            *(__nv_bfloat16*)(dh + d*272 + s*2) = hx;
            *(__nv_bfloat16*)(dl + d*272 + s*2) = __float2bfloat16_rn(rxv);
        }
    }
}

// sph tile [32 x 128] fp32 (integer-valued 0..7) -> packed uint8 idx
static __device__ __forceinline__ void sload(const float* __restrict__ sphb, int kt, int tid, float4* pre){
    #pragma unroll
    for (int i = 0; i < 4; ++i) {
        int c = i*256 + tid, row = c >> 5, cg = (c & 31)*4;
        pre[i] = __ldg((const float4*)(sphb + (size_t)row*Nn + kt*128 + cg));
    }
}
static __device__ __forceinline__ void sstore(const float4* pre, char* dst, int tid){
    #pragma unroll
    for (int i = 0; i < 4; ++i) {
        int c = i*256 + tid, row = c >> 5, cg = (c & 31)*4;
        uint32_t pk = (uint32_t)(int)pre[i].x | ((uint32_t)(int)pre[i].y << 8)
                    | ((uint32_t)(int)pre[i].z << 16) | ((uint32_t)(int)pre[i].w << 24);
        *(uint32_t*)(dst + row*128 + cg) = pk;
    }
}

__global__ void __launch_bounds__(256, 1)
bda_mma(const float* __restrict__ q, const float* __restrict__ k,
        const float* __restrict__ v, const float* __restrict__ sph,
        const float* __restrict__ hop, const float* __restrict__ gam,
        float* __restrict__ out_o, float* __restrict__ out_w)
{
    extern __shared__ __align__(16) char smem[];
    float* rs  = (float*)(smem + RS_OFF);
    float* tab = (float*)(smem + TAB_OFF);
    float* osm = (float*)(smem + OSM_OFF);

    const int tid = threadIdx.x;
    const int w = tid >> 5, lane = tid & 31;
    const int lg = lane >> 2, lt = lane & 3;

    const int blk = blockIdx.x;
    const int qt = blk & 31, h = (blk >> 5) & 7, b = blk >> 8;
    const int n0 = qt * TR;
    const bool isShort = (h < 4);

    const size_t bh = (size_t)b * Hn + h;
    const float* qb   = q + (bh * Nn + n0) * (size_t)Dn;
    const float* kb   = k + bh * (size_t)Nn * Dn;
    const float* vb   = v + bh * (size_t)Nn * Dn;
    const float* sphb = sph + ((size_t)b * Nn + n0) * Nn;

    // ---- init ----
    if (tid < 32) rs[tid] = 0.f;
    for (int i = tid; i < 2048; i += 256) osm[i] = 0.f;
    if (tid < 8) {
        float f = 1.0f;
        if (isShort) {
            float hopv = hop[h];
            float gm = 1.f / (1.f + __expf(-gam[h]));
            f = __powf(gm, fmaxf((float)tid - hopv, 0.f));
        }
        tab[tid] = f;
    }

    // stage Q (persistent), K tile 0, sph tile 0
    {
        float4 qp[2];
        kload<1>(qb, tid, qp);
        kstore<1>(qp, smem + QH_OFF, smem + QL_OFF, tid);
        float4 kp[8];
        kload<4>(kb, tid, kp);
        kstore<4>(kp, smem + KB_OFF, smem + KB_OFF + 18432, tid);
        if (isShort) {
            float4 sp[4];
            sload(sphb, 0, tid, sp);
            sstore(sp, smem + SPX_OFF, tid);
        }
    }
    __syncthreads();

    const float mytab = tab[lane & 7];

    // hoist Q fragments (constant over all k-tiles)
    uint32_t qhf[2][4][4], qlf[2][4][4];
    #pragma unroll
    for (int mi = 0; mi < 2; ++mi)
    #pragma unroll
    for (int kf = 0; kf < 4; ++kf) {
        int row = mi*16 + lg;
        int ko = (kf*16 + lt*2)*2;
        const char* ph = smem + QH_OFF;
        const char* pl = smem + QL_OFF;
        qhf[mi][kf][0] = *(const uint32_t*)(ph + row*144 + ko);
        qhf[mi][kf][1] = *(const uint32_t*)(ph + (row+8)*144 + ko);
        qhf[mi][kf][2] = *(const uint32_t*)(ph + row*144 + ko + 16);
        qhf[mi][kf][3] = *(const uint32_t*)(ph + (row+8)*144 + ko + 16);
        qlf[mi][kf][0] = *(const uint32_t*)(pl + row*144 + ko);
        qlf[mi][kf][1] = *(const uint32_t*)(pl + (row+8)*144 + ko);
        qlf[mi][kf][2] = *(const uint32_t*)(pl + row*144 + ko + 16);
        qlf[mi][kf][3] = *(const uint32_t*)(pl + (row+8)*144 + ko + 16);
    }

    float psum[4] = {0.f, 0.f, 0.f, 0.f};

    // ================= Phase A: S = QK^T -> exp -> Ebuf(hi/lo) =================
    for (int kt = 0; kt < NTILES; ++kt) {
        // prefetch next tile (LDG early; stores after compute)
        float4 kpre[8], spre[4];
        if (kt < NTILES-1) {
            kload<4>(kb + (size_t)(kt+1)*128*Dn, tid, kpre);
            if (isShort) sload(sphb, kt+1, tid, spre);
        }

        const char* Kh = smem + KB_OFF + (kt & 1)*36864;
        const char* Kl = Kh + 18432;

        float acc[2][2][4] = {};
        #pragma unroll
        for (int kf = 0; kf < 4; ++kf) {
            #pragma unroll
            for (int nf = 0; nf < 2; ++nf) {
                int n = w*16 + nf*8 + lg;
                int ko = (kf*16 + lt*2)*2;
                uint32_t bh0 = *(const uint32_t*)(Kh + n*144 + ko);
                uint32_t bh1 = *(const uint32_t*)(Kh + n*144 + ko + 16);
                uint32_t bl0 = *(const uint32_t*)(Kl + n*144 + ko);
                uint32_t bl1 = *(const uint32_t*)(Kl + n*144 + ko + 16);
                #pragma unroll
                for (int mi = 0; mi < 2; ++mi) {
                    mmabf(acc[mi][nf], qhf[mi][kf], bh0, bh1);
                    mmabf(acc[mi][nf], qlf[mi][kf], bh0, bh1);
                    mmabf(acc[mi][nf], qhf[mi][kf], bl0, bl1);
                }
            }
        }

        // epilogue: modulate, exp, split-store to Ebuf
        const char* spx = smem + SPX_OFF + (kt & 1)*4096;
        #pragma unroll
        for (int mi = 0; mi < 2; ++mi)
        #pragma unroll
        for (int nf = 0; nf < 2; ++nf)
        #pragma unroll
        for (int rp = 0; rp < 2; ++rp) {
            int row = mi*16 + lg + rp*8;
            int col = w*16 + nf*8 + lt*2;
            float s0 = acc[mi][nf][rp*2+0] * 0.125f;
            float s1 = acc[mi][nf][rp*2+1] * 0.125f;
            if (isShort) {
                uint32_t pp = *(const uint16_t*)(spx + row*128 + col);
                s0 *= __shfl_sync(0xffffffffu, mytab, (int)(pp & 7u));
                s1 *= __shfl_sync(0xffffffffu, mytab, (int)((pp >> 8) & 7u));
            }
            float e0 = __expf(s0), e1 = __expf(s1);   // bounded logits: no max pass
            psum[mi*2 + rp] += e0 + e1;
            __nv_bfloat162 hi = __float22bfloat162_rn(make_float2(e0, e1));
            float2 hf = __bfloat1622float2(hi);
            __nv_bfloat162 lo = __float22bfloat162_rn(make_float2(e0 - hf.x, e1 - hf.y));
            int eo = row*2064 + (kt*128 + col)*2;
            *(uint32_t*)(smem + EH_OFF + eo) = *(uint32_t*)&hi;
            *(uint32_t*)(smem + EL_OFF + eo) = *(uint32_t*)&lo;
        }

        if (kt < NTILES-1) {
            kstore<4>(kpre, smem + KB_OFF + ((kt+1) & 1)*36864,
                      smem + KB_OFF + ((kt+1) & 1)*36864 + 18432, tid);
            if (isShort) sstore(spre, smem + SPX_OFF + ((kt+1) & 1)*4096, tid);
        }
        __syncthreads();
    }

    // ================= row sums -> inverse =================
    #pragma unroll
    for (int i = 0; i < 4; ++i) {
        float s = psum[i];
        s += __shfl_xor_sync(0xffffffffu, s, 1);
        s += __shfl_xor_sync(0xffffffffu, s, 2);
        if (lt == 0) {
            int row = (i >> 1)*16 + lg + (i & 1)*8;
            atomicAdd(&rs[row], s);
        }
    }
    __syncthreads();
    if (tid < 32) rs[tid] = 1.0f / rs[tid];
    __syncthreads();

    // ================= Phase C: write normalized W =================
    {
        float* wbase = out_w + ((bh * Nn + n0) * (size_t)Nn);
        #pragma unroll 4
        for (int it = 0; it < 16; ++it) {
            int c = it*256 + tid;
            int row = c >> 7, pos = (c & 127)*8;
            uint4 hw = *(const uint4*)(smem + EH_OFF + row*2064 + pos*2);
            uint4 lw = *(const uint4*)(smem + EL_OFF + row*2064 + pos*2);
            float iv = rs[row];
            float o[8];
            const uint32_t hws[4] = {hw.x, hw.y, hw.z, hw.w};
            const uint32_t lws[4] = {lw.x, lw.y, lw.z, lw.w};
            #pragma unroll
            for (int j = 0; j < 4; ++j) {
                float2 hf = __bfloat1622float2(*(const __nv_bfloat162*)&hws[j]);
                float2 lf = __bfloat1622float2(*(const __nv_bfloat162*)&lws[j]);
                o[2*j]   = (hf.x + lf.x) * iv;
                o[2*j+1] = (hf.y + lf.y) * iv;
            }
            float* wp = wbase + (size_t)row*Nn + pos;
            *(float4*)wp       = make_float4(o[0], o[1], o[2], o[3]);
            *(float4*)(wp + 4) = make_float4(o[4], o[5], o[6], o[7]);
        }
    }

    // stage V^T tile 0
    {
        float4 vp[8];
        vload(vb, tid, vp);
        vstore(vp, smem + KB_OFF, smem + KB_OFF + 18432, tid);
    }
    __syncthreads();

    // ================= Phase D: O = E @ V (warps split over k) =================
    float acc2[2][8][4] = {};
    for (int kt = 0; kt < NTILES; ++kt) {
        float4 vpre[8];
        if (kt < NTILES-1) vload(vb + (size_t)(kt+1)*128*Dn, tid, vpre);

        const char* Vh = smem + KB_OFF + (kt & 1)*36864;
        const char* Vl = Vh + 18432;

        // A fragments from E: this warp's k16 slice
        uint32_t ahf[2][4], alf[2][4];
        int kg = kt*128 + w*16;
        #pragma unroll
        for (int mi = 0; mi < 2; ++mi) {
            int row = mi*16 + lg;
            int eo = (kg + lt*2)*2;
            ahf[mi][0] = *(const uint32_t*)(smem + EH_OFF + row*2064 + eo);
            ahf[mi][1] = *(const uint32_t*)(smem + EH_OFF + (row+8)*2064 + eo);
            ahf[mi][2] = *(const uint32_t*)(smem + EH_OFF + row*2064 + eo + 16);
            ahf[mi][3] = *(const uint32_t*)(smem + EH_OFF + (row+8)*2064 + eo + 16);
            alf[mi][0] = *(const uint32_t*)(smem + EL_OFF + row*2064 + eo);
            alf[mi][1] = *(const uint32_t*)(smem + EL_OFF + (row+8)*2064 + eo);
            alf[mi][2] = *(const uint32_t*)(smem + EL_OFF + row*2064 + eo + 16);
            alf[mi][3] = *(const uint32_t*)(smem + EL_OFF + (row+8)*2064 + eo + 16);
        }

        #pragma unroll
        for (int nf = 0; nf < 8; ++nf) {
            int n = nf*8 + lg;
            int ko = (w*16 + lt*2)*2;
            uint32_t bh0 = *(const uint32_t*)(Vh + n*272 + ko);
            uint32_t bh1 = *(const uint32_t*)(Vh + n*272 + ko + 16);
            uint32_t bl0 = *(const uint32_t*)(Vl + n*272 + ko);
            uint32_t bl1 = *(const uint32_t*)(Vl + n*272 + ko + 16);
            #pragma unroll
            for (int mi = 0; mi < 2; ++mi) {
                mmabf(acc2[mi][nf], ahf[mi], bh0, bh1);
                mmabf(acc2[mi][nf], alf[mi], bh0, bh1);
                mmabf(acc2[mi][nf], ahf[mi], bl0, bl1);
            }
        }

        if (kt < NTILES-1)
            vstore(vpre, smem + KB_OFF + ((kt+1) & 1)*36864,
                   smem + KB_OFF + ((kt+1) & 1)*36864 + 18432, tid);
        __syncthreads();
    }

    // cross-warp reduction of O partials
    #pragma unroll
    for (int mi = 0; mi < 2; ++mi)
    #pragma unroll
    for (int nf = 0; nf < 8; ++nf)
    #pragma unroll
    for (int rg = 0; rg < 4; ++rg) {
        int row = mi*16 + lg + (rg >> 1)*8;
        int col = nf*8 + lt*2 + (rg & 1);
        atomicAdd(&osm[row*64 + col], acc2[mi][nf][rg]);
    }
    __syncthreads();

    // write O
    {
        float* ob = out_o + ((bh * Nn + n0) * (size_t)Dn);
        #pragma unroll
        for (int it = 0; it < 2; ++it) {
            int c = it*256 + tid;           // 512 float4
            int row = c >> 4;
            float iv = rs[row];
            float4 vv = *(float4*)&osm[c*4];
            vv.x *= iv; vv.y *= iv; vv.z *= iv; vv.w *= iv;
            *(float4*)(ob + c*4) = vv;
        }
    }
}

extern "C" void kernel_launch(void* const* d_in, const int* in_sizes, int n_in,
                              void* d_out, int out_size)
{
    (void)in_sizes; (void)n_in; (void)out_size;
    const float* q   = (const float*)d_in[0];
    const float* k   = (const float*)d_in[1];
    const float* v   = (const float*)d_in[2];
    const float* sph = (const float*)d_in[3];
    const float* hop = (const float*)d_in[4];
    const float* gam = (const float*)d_in[5];

    float* out_o = (float*)d_out;
    float* out_w = out_o + (size_t)Bn * Hn * Nn * Dn;

    cudaFuncSetAttribute(bda_mma, cudaFuncAttributeMaxDynamicSharedMemorySize, SMEM_TOTAL);
    bda_mma<<<Bn*Hn*(Nn/TR), 256, SMEM_TOTAL>>>(q, k, v, sph, hop, gam, out_o, out_w);
}

// round 14
// speedup vs baseline: 2.5929x; 1.0083x over previous
#include <cuda_runtime.h>
#include <cuda_bf16.h>
#include <cstdint>

// BrainDecayAttention via mma.sync bf16 split-precision + MUFU/FFMA-split exp.
// B=16 H=8 N=1024 D=64 fp32. Grid 4096 = (b, h, 32-row q-tile), 256 threads.

#define Bn 16
#define Hn 8
#define Nn 1024
#define Dn 64
#define TR 32
#define NTILES 8

// ---- smem byte layout ----
#define RS_OFF   0                        // 32 floats
#define TAB_OFF  128                      // 8 floats
#define OSM_OFF  160                      // 2048 floats = 8192 B
#define SPX_OFF  8352                     // 2 x 4096 B sph idx tiles
#define QH_OFF   16544                    // 32 rows x 144 B = 4608
#define QL_OFF   (QH_OFF + 4608)
#define EH_OFF   (QL_OFF + 4608)          // 32 rows x 2064 B = 66048
#define EL_OFF   (EH_OFF + 66048)
#define KB_OFF   (EL_OFF + 66048)         // 2 buffers x 36864 (K hi/lo or V^T hi/lo)
#define SMEM_TOTAL (KB_OFF + 2*36864)     // 231584 B

static __device__ __forceinline__ void mmabf(float* c, const uint32_t* a,
                                             uint32_t b0, uint32_t b1){
    asm volatile("mma.sync.aligned.m16n8k16.row.col.f32.bf16.bf16.f32 "
        "{%0,%1,%2,%3}, {%4,%5,%6,%7}, {%8,%9}, {%0,%1,%2,%3};"
        : "+f"(c[0]), "+f"(c[1]), "+f"(c[2]), "+f"(c[3])
        : "r"(a[0]), "r"(a[1]), "r"(a[2]), "r"(a[3]), "r"(b0), "r"(b1));
}

// ---- packed f32x2 helpers (base Blackwell PTX, no 'a' feature) ----
static __device__ __forceinline__ uint64_t pk2(float x, float y){
    uint64_t r; asm("mov.b64 %0, {%1,%2};" : "=l"(r) : "f"(x), "f"(y)); return r;
}
static __device__ __forceinline__ void upk2(uint64_t p, float& x, float& y){
    asm("mov.b64 {%0,%1}, %2;" : "=f"(x), "=f"(y) : "l"(p));
}
static __device__ __forceinline__ uint64_t add2_(uint64_t a, uint64_t b){
    uint64_t r; asm("add.rn.f32x2 %0, %1, %2;" : "=l"(r) : "l"(a), "l"(b)); return r;
}
static __device__ __forceinline__ uint64_t fma2_(uint64_t a, uint64_t b, uint64_t c){
    uint64_t r; asm("fma.rn.f32x2 %0, %1, %2, %3;" : "=l"(r) : "l"(a), "l"(b), "l"(c)); return r;
}

static __device__ __forceinline__ float ex2m(float t){   // MUFU path
    float r; asm("ex2.approx.f32 %0, %1;" : "=f"(r) : "f"(t)); return r;
}

// 2^t for pair (t0,t1), |t| <= ~10, via magic-round + deg-4 poly on FMA pipe.
static __device__ __forceinline__ void exp2pair(float t0, float t1, float& e0, float& e1){
    const float MG = 12582912.f;                 // 1.5 * 2^23
    uint64_t t2 = pk2(t0, t1);
    uint64_t M2 = pk2(MG, MG);
    uint64_t z2 = add2_(t2, M2);                 // low bits hold rne(t)
    uint64_t nm = fma2_(z2, pk2(-1.f, -1.f), M2);// = -rne(t)
    uint64_t f2 = add2_(t2, nm);                 // f in [-0.5, 0.5]
    uint64_t p2 = fma2_(pk2(0.009618129f, 0.009618129f), f2,
                        pk2(0.055504109f, 0.055504109f));
    p2 = fma2_(p2, f2, pk2(0.240226507f, 0.240226507f));
    p2 = fma2_(p2, f2, pk2(0.693147181f, 0.693147181f));
    p2 = fma2_(p2, f2, pk2(1.0f, 1.0f));
    float z0, z1, p0, p1;
    upk2(z2, z0, z1);
    upk2(p2, p0, p1);
    e0 = __int_as_float(__float_as_int(p0) + (__float_as_int(z0) << 23));
    e1 = __int_as_float(__float_as_int(p1) + (__float_as_int(z1) << 23));
}

static __device__ __forceinline__ void split8(const float* f, uint32_t* hw, uint32_t* lw){
    #pragma unroll
    for (int j = 0; j < 4; ++j) {
        float2 xy = make_float2(f[2*j], f[2*j+1]);
        __nv_bfloat162 hh = __float22bfloat162_rn(xy);
        float2 hf = __bfloat1622float2(hh);
        __nv_bfloat162 ll = __float22bfloat162_rn(make_float2(xy.x - hf.x, xy.y - hf.y));
        hw[j] = *(uint32_t*)&hh;
        lw[j] = *(uint32_t*)&ll;
    }
}

// K-style tile [rows x 64] fp32 -> hi/lo bf16, row stride 144 B
template<int NCH>
static __device__ __forceinline__ void kload(const float* __restrict__ src, int tid, float4* pre){
    #pragma unroll
    for (int i = 0; i < NCH; ++i) {
        int c = i*256 + tid, row = c >> 3, u = c & 7;
        const float4* p = (const float4*)(src + row*64 + u*8);
        pre[2*i] = p[0]; pre[2*i+1] = p[1];
    }
}
template<int NCH>
static __device__ __forceinline__ void kstore(const float4* pre, char* dh, char* dl, int tid){
    #pragma unroll
    for (int i = 0; i < NCH; ++i) {
        int c = i*256 + tid, row = c >> 3, u = c & 7;
        float f[8] = {pre[2*i].x, pre[2*i].y, pre[2*i].z, pre[2*i].w,
                      pre[2*i+1].x, pre[2*i+1].y, pre[2*i+1].z, pre[2*i+1].w};
        uint32_t hw[4], lw[4];
        split8(f, hw, lw);
        *(uint4*)(dh + row*144 + u*16) = make_uint4(hw[0], hw[1], hw[2], hw[3]);
        *(uint4*)(dl + row*144 + u*16) = make_uint4(lw[0], lw[1], lw[2], lw[3]);
    }
}

// V tile [128 s x 64 d] fp32 -> V^T hi/lo bf16 [64 d x 128 s], row stride 272 B
static __device__ __forceinline__ void vload(const float* __restrict__ vsrc, int tid, float4* pre){
    int s = tid >> 1, d0 = (tid & 1)*32;
    const float4* p = (const float4*)(vsrc + s*64 + d0);
    #pragma unroll
    for (int j = 0; j < 8; ++j) pre[j] = p[j];
}
static __device__ __forceinline__ void vstore(const float4* pre, char* dh, char* dl, int tid){
    int s = tid >> 1, d0 = (tid & 1)*32;
    #pragma unroll
    for (int j = 0; j < 8; ++j) {
        float f[4] = {pre[j].x, pre[j].y, pre[j].z, pre[j].w};
        #pragma unroll
        for (int e = 0; e < 4; ++e) {
            int d = d0 + j*4 + e;
            __nv_bfloat16 hx = __float2bfloat16_rn(f[e]);
            float rxv = f[e] - __bfloat162float(hx);
            *(__nv_bfloat16*)(dh + d*272 + s*2) = hx;
            *(__nv_bfloat16*)(dl + d*272 + s*2) = __float2bfloat16_rn(rxv);
        }
    }
}

// sph tile [32 x 128] fp32 (integer-valued 0..7) -> packed uint8 idx
static __device__ __forceinline__ void sload(const float* __restrict__ sphb, int kt, int tid, float4* pre){
    #pragma unroll
    for (int i = 0; i < 4; ++i) {
        int c = i*256 + tid, row = c >> 5, cg = (c & 31)*4;
        pre[i] = __ldg((const float4*)(sphb + (size_t)row*Nn + kt*128 + cg));
    }
}
static __device__ __forceinline__ void sstore(const float4* pre, char* dst, int tid){
    #pragma unroll
    for (int i = 0; i < 4; ++i) {
        int c = i*256 + tid, row = c >> 5, cg = (c & 31)*4;
        uint32_t pk = (uint32_t)(int)pre[i].x | ((uint32_t)(int)pre[i].y << 8)
                    | ((uint32_t)(int)pre[i].z << 16) | ((uint32_t)(int)pre[i].w << 24);
        *(uint32_t*)(dst + row*128 + cg) = pk;
    }
}

__global__ void __launch_bounds__(256, 1)
bda_mma(const float* __restrict__ q, const float* __restrict__ k,
        const float* __restrict__ v, const float* __restrict__ sph,
        const float* __restrict__ hop, const float* __restrict__ gam,
        float* __restrict__ out_o, float* __restrict__ out_w)
{
    extern __shared__ __align__(16) char smem[];
    float* rs  = (float*)(smem + RS_OFF);
    float* tab = (float*)(smem + TAB_OFF);
    float* osm = (float*)(smem + OSM_OFF);

    const int tid = threadIdx.x;
    const int w = tid >> 5, lane = tid & 31;
    const int lg = lane >> 2, lt = lane & 3;

    const int blk = blockIdx.x;
    const int qt = blk & 31, h = (blk >> 5) & 7, b = blk >> 8;
    const int n0 = qt * TR;
    const bool isShort = (h < 4);

    const size_t bh = (size_t)b * Hn + h;
    const float* qb   = q + (bh * Nn + n0) * (size_t)Dn;
    const float* kb   = k + bh * (size_t)Nn * Dn;
    const float* vb   = v + bh * (size_t)Nn * Dn;
    const float* sphb = sph + ((size_t)b * Nn + n0) * Nn;

    // ---- init ----
    if (tid < 32) rs[tid] = 0.f;
    for (int i = tid; i < 2048; i += 256) osm[i] = 0.f;
    if (tid < 8) {
        float f = 0.18033688011f;               // 0.125 * log2(e)
        if (isShort) {
            float hopv = hop[h];
            float gm = 1.f / (1.f + __expf(-gam[h]));
            f *= __powf(gm, fmaxf((float)tid - hopv, 0.f));
        }
        tab[tid] = f;
    }

    // stage Q (persistent), K tile 0, sph tile 0
    {
        float4 qp[2];
        kload<1>(qb, tid, qp);
        kstore<1>(qp, smem + QH_OFF, smem + QL_OFF, tid);
        float4 kp[8];
        kload<4>(kb, tid, kp);
        kstore<4>(kp, smem + KB_OFF, smem + KB_OFF + 18432, tid);
        if (isShort) {
            float4 sp[4];
            sload(sphb, 0, tid, sp);
            sstore(sp, smem + SPX_OFF, tid);
        }
    }
    __syncthreads();

    const float mytab = tab[lane & 7];

    // hoist Q fragments (constant over all k-tiles)
    uint32_t qhf[2][4][4], qlf[2][4][4];
    #pragma unroll
    for (int mi = 0; mi < 2; ++mi)
    #pragma unroll
    for (int kf = 0; kf < 4; ++kf) {
        int row = mi*16 + lg;
        int ko = (kf*16 + lt*2)*2;
        const char* ph = smem + QH_OFF;
        const char* pl = smem + QL_OFF;
        qhf[mi][kf][0] = *(const uint32_t*)(ph + row*144 + ko);
        qhf[mi][kf][1] = *(const uint32_t*)(ph + (row+8)*144 + ko);
        qhf[mi][kf][2] = *(const uint32_t*)(ph + row*144 + ko + 16);
        qhf[mi][kf][3] = *(const uint32_t*)(ph + (row+8)*144 + ko + 16);
        qlf[mi][kf][0] = *(const uint32_t*)(pl + row*144 + ko);
        qlf[mi][kf][1] = *(const uint32_t*)(pl + (row+8)*144 + ko);
        qlf[mi][kf][2] = *(const uint32_t*)(pl + row*144 + ko + 16);
        qlf[mi][kf][3] = *(const uint32_t*)(pl + (row+8)*144 + ko + 16);
    }

    float psum[4] = {0.f, 0.f, 0.f, 0.f};

    // ================= Phase A: S = QK^T -> exp -> Ebuf(hi/lo) =================
    for (int kt = 0; kt < NTILES; ++kt) {
        // prefetch next tile (LDG early; stores after compute)
        float4 kpre[8], spre[4];
        if (kt < NTILES-1) {
            kload<4>(kb + (size_t)(kt+1)*128*Dn, tid, kpre);
            if (isShort) sload(sphb, kt+1, tid, spre);
        }

        const char* Kh = smem + KB_OFF + (kt & 1)*36864;
        const char* Kl = Kh + 18432;

        float acc[2][2][4] = {};
        #pragma unroll
        for (int kf = 0; kf < 4; ++kf) {
            #pragma unroll
            for (int nf = 0; nf < 2; ++nf) {
                int n = w*16 + nf*8 + lg;
                int ko = (kf*16 + lt*2)*2;
                uint32_t bh0 = *(const uint32_t*)(Kh + n*144 + ko);
                uint32_t bh1 = *(const uint32_t*)(Kh + n*144 + ko + 16);
                uint32_t bl0 = *(const uint32_t*)(Kl + n*144 + ko);
                uint32_t bl1 = *(const uint32_t*)(Kl + n*144 + ko + 16);
                #pragma unroll
                for (int mi = 0; mi < 2; ++mi) {
                    mmabf(acc[mi][nf], qhf[mi][kf], bh0, bh1);
                    mmabf(acc[mi][nf], qlf[mi][kf], bh0, bh1);
                    mmabf(acc[mi][nf], qhf[mi][kf], bl0, bl1);
                }
            }
        }

        // epilogue: modulate, exp (5/8 MUFU, 3/8 FMA-pipe poly), split-store
        const char* spx = smem + SPX_OFF + (kt & 1)*4096;
        #pragma unroll
        for (int mi = 0; mi < 2; ++mi)
        #pragma unroll
        for (int nf = 0; nf < 2; ++nf)
        #pragma unroll
        for (int rp = 0; rp < 2; ++rp) {
            const int it = mi*4 + nf*2 + rp;
            int row = mi*16 + lg + rp*8;
            int col = w*16 + nf*8 + lt*2;
            float t0 = acc[mi][nf][rp*2+0];
            float t1 = acc[mi][nf][rp*2+1];
            if (isShort) {
                uint32_t pp = *(const uint16_t*)(spx + row*128 + col);
                t0 *= __shfl_sync(0xffffffffu, mytab, (int)(pp & 7u));
                t1 *= __shfl_sync(0xffffffffu, mytab, (int)((pp >> 8) & 7u));
            } else {
                t0 *= 0.18033688011f;
                t1 *= 0.18033688011f;
            }
            float e0, e1;
            if (it < 5) { e0 = ex2m(t0); e1 = ex2m(t1); }    // MUFU
            else        { exp2pair(t0, t1, e0, e1); }         // FMA-pipe poly
            psum[mi*2 + rp] += e0 + e1;
            __nv_bfloat162 hi = __float22bfloat162_rn(make_float2(e0, e1));
            float2 hf = __bfloat1622float2(hi);
            __nv_bfloat162 lo = __float22bfloat162_rn(make_float2(e0 - hf.x, e1 - hf.y));
            int eo = row*2064 + (kt*128 + col)*2;
            *(uint32_t*)(smem + EH_OFF + eo) = *(uint32_t*)&hi;
            *(uint32_t*)(smem + EL_OFF + eo) = *(uint32_t*)&lo;
        }

        if (kt < NTILES-1) {
            kstore<4>(kpre, smem + KB_OFF + ((kt+1) & 1)*36864,
                      smem + KB_OFF + ((kt+1) & 1)*36864 + 18432, tid);
            if (isShort) sstore(spre, smem + SPX_OFF + ((kt+1) & 1)*4096, tid);
        }
        __syncthreads();
    }

    // ================= row sums -> inverse =================
    #pragma unroll
    for (int i = 0; i < 4; ++i) {
        float s = psum[i];
        s += __shfl_xor_sync(0xffffffffu, s, 1);
        s += __shfl_xor_sync(0xffffffffu, s, 2);
        if (lt == 0) {
            int row = (i >> 1)*16 + lg + (i & 1)*8;
            atomicAdd(&rs[row], s);
        }
    }
    __syncthreads();
    if (tid < 32) rs[tid] = 1.0f / rs[tid];
    __syncthreads();

    // ================= Phase C: write normalized W =================
    {
        float* wbase = out_w + ((bh * Nn + n0) * (size_t)Nn);
        #pragma unroll 4
        for (int it = 0; it < 16; ++it) {
            int c = it*256 + tid;
            int row = c >> 7, pos = (c & 127)*8;
            uint4 hw = *(const uint4*)(smem + EH_OFF + row*2064 + pos*2);
            uint4 lw = *(const uint4*)(smem + EL_OFF + row*2064 + pos*2);
            float iv = rs[row];
            float o[8];
            const uint32_t hws[4] = {hw.x, hw.y, hw.z, hw.w};
            const uint32_t lws[4] = {lw.x, lw.y, lw.z, lw.w};
            #pragma unroll
            for (int j = 0; j < 4; ++j) {
                float2 hf = __bfloat1622float2(*(const __nv_bfloat162*)&hws[j]);
                float2 lf = __bfloat1622float2(*(const __nv_bfloat162*)&lws[j]);
                o[2*j]   = (hf.x + lf.x) * iv;
                o[2*j+1] = (hf.y + lf.y) * iv;
            }
            float* wp = wbase + (size_t)row*Nn + pos;
            *(float4*)wp       = make_float4(o[0], o[1], o[2], o[3]);
            *(float4*)(wp + 4) = make_float4(o[4], o[5], o[6], o[7]);
        }
    }

    // stage V^T tile 0
    {
        float4 vp[8];
        vload(vb, tid, vp);
        vstore(vp, smem + KB_OFF, smem + KB_OFF + 18432, tid);
    }
    __syncthreads();

    // ================= Phase D: O = E @ V (warps split over k) =================
    float acc2[2][8][4] = {};
    for (int kt = 0; kt < NTILES; ++kt) {
        float4 vpre[8];
        if (kt < NTILES-1) vload(vb + (size_t)(kt+1)*128*Dn, tid, vpre);

        const char* Vh = smem + KB_OFF + (kt & 1)*36864;
        const char* Vl = Vh + 18432;

        // A fragments from E: this warp's k16 slice
        uint32_t ahf[2][4], alf[2][4];
        int kg = kt*128 + w*16;
        #pragma unroll
        for (int mi = 0; mi < 2; ++mi) {
            int row = mi*16 + lg;
            int eo = (kg + lt*2)*2;
            ahf[mi][0] = *(const uint32_t*)(smem + EH_OFF + row*2064 + eo);
            ahf[mi][1] = *(const uint32_t*)(smem + EH_OFF + (row+8)*2064 + eo);
            ahf[mi][2] = *(const uint32_t*)(smem + EH_OFF + row*2064 + eo + 16);
            ahf[mi][3] = *(const uint32_t*)(smem + EH_OFF + (row+8)*2064 + eo + 16);
            alf[mi][0] = *(const uint32_t*)(smem + EL_OFF + row*2064 + eo);
            alf[mi][1] = *(const uint32_t*)(smem + EL_OFF + (row+8)*2064 + eo);
            alf[mi][2] = *(const uint32_t*)(smem + EL_OFF + row*2064 + eo + 16);
            alf[mi][3] = *(const uint32_t*)(smem + EL_OFF + (row+8)*2064 + eo + 16);
        }

        #pragma unroll
        for (int nf = 0; nf < 8; ++nf) {
            int n = nf*8 + lg;
            int ko = (w*16 + lt*2)*2;
            uint32_t bh0 = *(const uint32_t*)(Vh + n*272 + ko);
            uint32_t bh1 = *(const uint32_t*)(Vh + n*272 + ko + 16);
            uint32_t bl0 = *(const uint32_t*)(Vl + n*272 + ko);
            uint32_t bl1 = *(const uint32_t*)(Vl + n*272 + ko + 16);
            #pragma unroll
            for (int mi = 0; mi < 2; ++mi) {
                mmabf(acc2[mi][nf], ahf[mi], bh0, bh1);
                mmabf(acc2[mi][nf], alf[mi], bh0, bh1);
                mmabf(acc2[mi][nf], ahf[mi], bl0, bl1);
            }
        }

        if (kt < NTILES-1)
            vstore(vpre, smem + KB_OFF + ((kt+1) & 1)*36864,
                   smem + KB_OFF + ((kt+1) & 1)*36864 + 18432, tid);
        __syncthreads();
    }

    // cross-warp reduction of O partials
    #pragma unroll
    for (int mi = 0; mi < 2; ++mi)
    #pragma unroll
    for (int nf = 0; nf < 8; ++nf)
    #pragma unroll
    for (int rg = 0; rg < 4; ++rg) {
        int row = mi*16 + lg + (rg >> 1)*8;
        int col = nf*8 + lt*2 + (rg & 1);
        atomicAdd(&osm[row*64 + col], acc2[mi][nf][rg]);
    }
    __syncthreads();

    // write O
    {
        float* ob = out_o + ((bh * Nn + n0) * (size_t)Dn);
        #pragma unroll
        for (int it = 0; it < 2; ++it) {
            int c = it*256 + tid;           // 512 float4
            int row = c >> 4;
            float iv = rs[row];
            float4 vv = *(float4*)&osm[c*4];
            vv.x *= iv; vv.y *= iv; vv.z *= iv; vv.w *= iv;
            *(float4*)(ob + c*4) = vv;
        }
    }
}

extern "C" void kernel_launch(void* const* d_in, const int* in_sizes, int n_in,
                              void* d_out, int out_size)
{
    (void)in_sizes; (void)n_in; (void)out_size;
    const float* q   = (const float*)d_in[0];
    const float* k   = (const float*)d_in[1];
    const float* v   = (const float*)d_in[2];
    const float* sph = (const float*)d_in[3];
    const float* hop = (const float*)d_in[4];
    const float* gam = (const float*)d_in[5];

    float* out_o = (float*)d_out;
    float* out_w = out_o + (size_t)Bn * Hn * Nn * Dn;

    cudaFuncSetAttribute(bda_mma, cudaFuncAttributeMaxDynamicSharedMemorySize, SMEM_TOTAL);
    bda_mma<<<Bn*Hn*(Nn/TR), 256, SMEM_TOTAL>>>(q, k, v, sph, hop, gam, out_o, out_w);
}